// round 12
// baseline (speedup 1.0000x reference)
#include <cuda_runtime.h>
#include <mma.h>
#include <math.h>

using namespace nvcuda;

// ---------------------------------------------------------------------------
// RiemannianGNN, 2-layer Poincare GNN — split kernels.
//   gemm:  msg = x @ W   (tf32 WMMA, W resident; cp.async 4-buffer ring,
//                         prefetch distance 2, ONE barrier per 16-row tile)
//   agg:   combined = sum_k (w*maskfac[adj]) * msg[adj],  * mask[n]
//          out = relu(expmap(.)*mask)*mask  (+ fused logmap*mask for layer 0)
// ---------------------------------------------------------------------------

#define NMAX 50000
#define DD 128
#define KK 32
#define LDSW 132        // padded W stride (floats)
#define LDSA 132        // padded A stride
#define ATILE 16        // rows per pipelined A tile (N % 16 == 0)

__device__ __align__(16) float g_msg[NMAX * DD];
__device__ __align__(16) float g_x[NMAX * DD];

__device__ __forceinline__ void cp_async16(float* smem_dst, const float* gsrc) {
    unsigned s = (unsigned)__cvta_generic_to_shared(smem_dst);
    asm volatile("cp.async.cg.shared.global [%0], [%1], 16;" :: "r"(s), "l"(gsrc));
}
__device__ __forceinline__ void cp_commit() {
    asm volatile("cp.async.commit_group;");
}
__device__ __forceinline__ void cp_wait2() {
    asm volatile("cp.async.wait_group 2;");
}

// ---------------- persistent pipelined GEMM: out = x @ W -------------------
// 8 warps, each owns cols w*16 of the 16x128 tile.
__global__ __launch_bounds__(256) void gemm_kernel(
    const float* __restrict__ x, const float* __restrict__ W,
    float* __restrict__ out, int N)
{
    extern __shared__ float sm[];
    float* Ws = sm;                          // 128 x LDSW
    float* Ab[4];
    Ab[0] = sm + DD * LDSW;
    Ab[1] = Ab[0] + ATILE * LDSA;
    Ab[2] = Ab[1] + ATILE * LDSA;
    Ab[3] = Ab[2] + ATILE * LDSA;

    const int tid = threadIdx.x;
    const int w   = tid >> 5;

    // stage W once (convert to tf32)
    for (int i = tid; i < DD * DD / 4; i += 256) {
        int r = i >> 5, c4 = i & 31;
        float4 v = ((const float4*)W)[r * 32 + c4];
        float* dst = Ws + r * LDSW + c4 * 4;
        dst[0] = wmma::__float_to_tf32(v.x);
        dst[1] = wmma::__float_to_tf32(v.y);
        dst[2] = wmma::__float_to_tf32(v.z);
        dst[3] = wmma::__float_to_tf32(v.w);
    }

    const int G = gridDim.x;
    const int nTiles = (N + ATILE - 1) / ATILE;   // N%16==0: exact

    // per-thread slice: 16 rows * 32 f4 = 512 f4 / 256 thr = 2 each
    auto loadA = [&](int t, float* buf) {
        if (t >= nTiles) return;
        const int t0 = t * ATILE;
        #pragma unroll
        for (int i = 0; i < 2; i++) {
            int idx = tid + i * 256;
            int r = idx >> 5, c4 = idx & 31;
            cp_async16(buf + r * LDSA + c4 * 4,
                       x + (size_t)(t0 + r) * DD + c4 * 4);
        }
    };

    // prologue: prefetch 2 tiles ahead
    loadA(blockIdx.x,     Ab[0]); cp_commit();
    loadA(blockIdx.x + G, Ab[1]); cp_commit();
    __syncthreads();     // W staged + prologue commits ordered for all

    int it = 0;
    for (int tile = blockIdx.x; tile < nTiles; tile += G, it++) {
        loadA(tile + 2 * G, Ab[(it + 2) & 3]);
        cp_commit();
        cp_wait2();                    // group for 'tile' complete
        __syncthreads();               // ring safety: orders prior-iter reads

        const float* A = Ab[it & 3];

        wmma::fragment<wmma::matrix_a, 16, 16, 8, wmma::precision::tf32, wmma::row_major> aF;
        wmma::fragment<wmma::matrix_b, 16, 16, 8, wmma::precision::tf32, wmma::row_major> bF;
        wmma::fragment<wmma::accumulator, 16, 16, 8, float> acc;
        wmma::fill_fragment(acc, 0.0f);

        #pragma unroll
        for (int ks = 0; ks < DD / 8; ks++) {
            const int kOff = ks * 8;
            wmma::load_matrix_sync(aF, A + kOff, LDSA);
            wmma::load_matrix_sync(bF, Ws + kOff * LDSW + w * 16, LDSW);
            wmma::mma_sync(acc, aF, bF, acc);
        }

        wmma::store_matrix_sync(out + (size_t)tile * ATILE * DD + w * 16,
                                acc, DD, wmma::mem_row_major);
    }
}

// ---------------- Aggregation + expmap + relu (+ fused logmap) -------------
// one warp per node; lane l holds cols 4l..4l+3 (LDG.128 per gathered row)
__global__ __launch_bounds__(256, 8) void agg_kernel(
    const float* __restrict__ msg, const int* __restrict__ adj,
    const float* __restrict__ wgt, const float* __restrict__ mask,
    float* __restrict__ out, int N, int layer0)
{
    const int warp = (blockIdx.x * blockDim.x + threadIdx.x) >> 5;
    const int lane = threadIdx.x & 31;
    if (warp >= N) return;

    const int   myIdx = adj[warp * KK + lane];
    const float ma    = mask[myIdx];
    // fold t-mask and msg-mask of the gathered rows into the weight
    const float myW   = wgt[warp * KK + lane] * (layer0 ? ma * ma : ma);

    float4 acc = make_float4(0.f, 0.f, 0.f, 0.f);
    #pragma unroll
    for (int j = 0; j < KK; j++) {
        int   nb = __shfl_sync(0xffffffffu, myIdx, j);
        float wj = __shfl_sync(0xffffffffu, myW,   j);
        float4 v = __ldg(((const float4*)(msg + (size_t)nb * DD)) + lane);
        acc.x = fmaf(wj, v.x, acc.x);
        acc.y = fmaf(wj, v.y, acc.y);
        acc.z = fmaf(wj, v.z, acc.z);
        acc.w = fmaf(wj, v.w, acc.w);
    }

    const float m = mask[warp];
    acc.x *= m; acc.y *= m; acc.z *= m; acc.w *= m;   // combined = (...)*mask

    // expmap_zero: tanh(clip(||v||,eps,15)) * v / max(||v||,eps), then *mask
    float ss = acc.x * acc.x + acc.y * acc.y + acc.z * acc.z + acc.w * acc.w;
    #pragma unroll
    for (int o = 16; o > 0; o >>= 1) ss += __shfl_xor_sync(0xffffffffu, ss, o);
    float n1  = sqrtf(ss);
    float nc1 = fminf(fmaxf(n1, 1e-5f), 15.0f);
    float s1  = tanhf(nc1) / fmaxf(n1, 1e-5f) * m;

    float4 e;
    e.x = fmaxf(acc.x * s1, 0.f) * m;
    e.y = fmaxf(acc.y * s1, 0.f) * m;
    e.z = fmaxf(acc.z * s1, 0.f) * m;
    e.w = fmaxf(acc.w * s1, 0.f) * m;

    if (layer0) {
        // next layer's logmap: atanh(clip(||y||,eps,1-1e-5))*y/max(||y||,eps)*mask
        float ss2 = e.x * e.x + e.y * e.y + e.z * e.z + e.w * e.w;
        #pragma unroll
        for (int o = 16; o > 0; o >>= 1) ss2 += __shfl_xor_sync(0xffffffffu, ss2, o);
        float n2  = sqrtf(ss2);
        float nc2 = fminf(fmaxf(n2, 1e-5f), 1.0f - 1e-5f);
        float s2  = atanhf(nc2) / fmaxf(n2, 1e-5f) * m;
        e.x *= s2; e.y *= s2; e.z *= s2; e.w *= s2;
    }

    ((float4*)out)[warp * 32 + lane] = e;
}

// ---------------------------------------------------------------------------

extern "C" void kernel_launch(void* const* d_in, const int* in_sizes, int n_in,
                              void* d_out, int out_size)
{
    const float* node_repr = (const float*)d_in[0];   // [N,128]
    const int*   adj_mat   = (const int*)  d_in[1];   // [N,32]
    const float* weight    = (const float*)d_in[2];   // [N,32]
    const float* mask      = (const float*)d_in[3];   // [N,1]
    const float* msg_w     = (const float*)d_in[4];   // [2,128,128]
    float*       out       = (float*)d_out;

    const int N = in_sizes[0] / DD;

    float* msg; float* xbuf;
    cudaGetSymbolAddress((void**)&msg,  g_msg);
    cudaGetSymbolAddress((void**)&xbuf, g_x);

    const int smemBytes = (DD * LDSW + 4 * ATILE * LDSA) * sizeof(float); // ~101.4 KB
    static int attrSet = 0;
    if (!attrSet) {
        cudaFuncSetAttribute(gemm_kernel,
                             cudaFuncAttributeMaxDynamicSharedMemorySize, smemBytes);
        // agg uses no smem: maximize L1 to raise gather hit rate
        cudaFuncSetAttribute(agg_kernel,
                             cudaFuncAttributePreferredSharedMemoryCarveout, 0);
        attrSet = 1;
    }

    const int nTiles = (N + ATILE - 1) / ATILE;
    int gemmBlocks = 296;                // persistent, 2 CTA/SM
    if (gemmBlocks > nTiles) gemmBlocks = nTiles;
    const int aggBlocks = (N * 32 + 255) / 256;

    const float* W0 = msg_w;
    const float* W1 = msg_w + DD * DD;

    gemm_kernel<<<gemmBlocks, 256, smemBytes>>>(node_repr, W0, msg, N);
    agg_kernel <<<aggBlocks, 256>>>(msg, adj_mat, weight, mask, xbuf, N, 1);
    gemm_kernel<<<gemmBlocks, 256, smemBytes>>>(xbuf, W1, msg, N);
    agg_kernel <<<aggBlocks, 256>>>(msg, adj_mat, weight, mask, out, N, 0);
}

// round 14
// speedup vs baseline: 1.3238x; 1.3238x over previous
#include <cuda_runtime.h>
#include <mma.h>
#include <math.h>

// ---------------------------------------------------------------------------
// RiemannianGNN, 2-layer Poincare GNN — split kernels.
//   gemm:  msg = x @ W   (raw mma.sync tf32 m16n8k8; B (=W) entirely in
//          registers, loaded once; A via cp.async 4-buffer ring, depth 2;
//          k-loop = A-LDS + 64 independent MMAs, no B smem traffic at all)
//   agg:   combined = sum_k (w*maskfac[adj]) * msg[adj],  * mask[n]
//          out = relu(expmap(.)*mask)*mask  (+ fused logmap*mask for layer 0)
// ---------------------------------------------------------------------------

#define NMAX 50000
#define DD 128
#define KK 32
#define LDSA 132        // padded A stride (floats)
#define ATILE 32        // rows per pipelined A tile

__device__ __align__(16) float g_msg[NMAX * DD];
__device__ __align__(16) float g_x[NMAX * DD];

__device__ __forceinline__ void cp_async16(float* smem_dst, const float* gsrc) {
    unsigned s = (unsigned)__cvta_generic_to_shared(smem_dst);
    asm volatile("cp.async.cg.shared.global [%0], [%1], 16;" :: "r"(s), "l"(gsrc));
}
__device__ __forceinline__ void cp_commit() {
    asm volatile("cp.async.commit_group;");
}
__device__ __forceinline__ void cp_wait2() {
    asm volatile("cp.async.wait_group 2;");
}

// D(16x8) += A(16x8,row) * B(8x8,col), tf32 inputs, f32 accum
__device__ __forceinline__ void mma_tf32(float* d,
    unsigned a0, unsigned a1, unsigned a2, unsigned a3,
    unsigned b0, unsigned b1)
{
    asm volatile(
        "mma.sync.aligned.m16n8k8.row.col.f32.tf32.tf32.f32 "
        "{%0,%1,%2,%3}, {%4,%5,%6,%7}, {%8,%9}, {%0,%1,%2,%3};"
        : "+f"(d[0]), "+f"(d[1]), "+f"(d[2]), "+f"(d[3])
        : "r"(a0), "r"(a1), "r"(a2), "r"(a3), "r"(b0), "r"(b1));
}

__device__ __forceinline__ unsigned to_tf32_bits(float v) {
    return __float_as_uint(nvcuda::wmma::__float_to_tf32(v));
}

// ---------------- persistent GEMM: out = x @ W, B-in-registers -------------
// 8 warps; warp w owns output cols [w*16, w*16+16): 2 n8 groups.
// Per 32-row tile: 2 row-groups x 16 k-steps x 2 n-groups = 64 MMAs/warp.
__global__ __launch_bounds__(256, 2) void gemm_kernel(
    const float* __restrict__ x, const float* __restrict__ W,
    float* __restrict__ out, int N)
{
    extern __shared__ float sm[];
    float* Ab[4];
    Ab[0] = sm;
    Ab[1] = Ab[0] + ATILE * LDSA;
    Ab[2] = Ab[1] + ATILE * LDSA;
    Ab[3] = Ab[2] + ATILE * LDSA;

    const int tid  = threadIdx.x;
    const int w    = tid >> 5;
    const int lane = tid & 31;
    const int g    = lane >> 2;      // groupID
    const int t    = lane & 3;       // threadID_in_group
    const int n0   = w * 16;         // this warp's output column base

    // ---- B fragments in registers, loaded once from global W --------------
    // For mma.m16n8k8.row.col, B (8x8, col-major view = W^T slice):
    //   b0 holds B[k = t    ][n = g]  -> W[(ks*8 + t)    *DD + n0+ng*8+g]
    //   b1 holds B[k = t + 4][n = g]  -> W[(ks*8 + t + 4)*DD + n0+ng*8+g]
    unsigned breg[16][2][2];
    #pragma unroll
    for (int ks = 0; ks < 16; ks++) {
        const int k0 = ks * 8 + t;
        #pragma unroll
        for (int ng = 0; ng < 2; ng++) {
            const int col = n0 + ng * 8 + g;
            breg[ks][ng][0] = to_tf32_bits(W[(size_t)k0       * DD + col]);
            breg[ks][ng][1] = to_tf32_bits(W[(size_t)(k0 + 4) * DD + col]);
        }
    }

    const int G = gridDim.x;
    const int nTiles = (N + ATILE - 1) / ATILE;

    // per-thread slice of A tile: 32 rows * 32 f4 / 256 thr = 4 f4 each
    auto loadA = [&](int tt, float* buf) {
        if (tt >= nTiles) return;
        const int t0 = tt * ATILE;
        #pragma unroll
        for (int i = 0; i < 4; i++) {
            int idx = tid + i * 256;
            int r = idx >> 5, c4 = idx & 31;
            int n = t0 + r;
            float* dst = buf + r * LDSA + c4 * 4;
            if (n < N) {
                cp_async16(dst, x + (size_t)n * DD + c4 * 4);
            } else {
                dst[0] = 0.f; dst[1] = 0.f; dst[2] = 0.f; dst[3] = 0.f;
            }
        }
    };

    // prologue: prefetch 2 tiles ahead
    loadA(blockIdx.x,     Ab[0]); cp_commit();
    loadA(blockIdx.x + G, Ab[1]); cp_commit();

    int it = 0;
    for (int tile = blockIdx.x; tile < nTiles; tile += G, it++) {
        loadA(tile + 2 * G, Ab[(it + 2) & 3]);
        cp_commit();
        cp_wait2();                  // group for 'tile' complete
        __syncthreads();             // smem visible + ring-reuse ordering

        const float* A = Ab[it & 3];
        // A fragment for lane: a0=A[g][kt], a1=A[g+8][kt], a2=A[g][kt+4], a3=A[g+8][kt+4]
        const float* Al = A + g * LDSA + t;

        float acc[2][2][4];
        #pragma unroll
        for (int rg = 0; rg < 2; rg++)
            #pragma unroll
            for (int ng = 0; ng < 2; ng++)
                #pragma unroll
                for (int i = 0; i < 4; i++) acc[rg][ng][i] = 0.f;

        #pragma unroll
        for (int ks = 0; ks < 16; ks++) {
            #pragma unroll
            for (int rg = 0; rg < 2; rg++) {
                const float* Ar = Al + rg * 16 * LDSA + ks * 8;
                // fp32 bits read from smem; tensor core truncates to tf32
                unsigned a0 = __float_as_uint(Ar[0]);
                unsigned a1 = __float_as_uint(Ar[8 * LDSA]);
                unsigned a2 = __float_as_uint(Ar[4]);
                unsigned a3 = __float_as_uint(Ar[8 * LDSA + 4]);
                #pragma unroll
                for (int ng = 0; ng < 2; ng++)
                    mma_tf32(acc[rg][ng], a0, a1, a2, a3,
                             breg[ks][ng][0], breg[ks][ng][1]);
            }
        }

        // epilogue: STG.64 per (rg, ng, half); d-regs {0,1}->row g, {2,3}->row g+8
        const int t0 = tile * ATILE;
        #pragma unroll
        for (int rg = 0; rg < 2; rg++) {
            #pragma unroll
            for (int ng = 0; ng < 2; ng++) {
                const int row = t0 + rg * 16 + g;
                const int col = n0 + ng * 8 + 2 * t;
                if (row < N) {
                    float2 lo = make_float2(acc[rg][ng][0], acc[rg][ng][1]);
                    *(float2*)(out + (size_t)row * DD + col) = lo;
                }
                if (row + 8 < N) {
                    float2 hi = make_float2(acc[rg][ng][2], acc[rg][ng][3]);
                    *(float2*)(out + (size_t)(row + 8) * DD + col) = hi;
                }
            }
        }
    }
}

// ---------------- Aggregation + expmap + relu (+ fused logmap) -------------
// one warp per node; lane l holds cols 4l..4l+3 (LDG.128 per gathered row)
__global__ __launch_bounds__(256, 8) void agg_kernel(
    const float* __restrict__ msg, const int* __restrict__ adj,
    const float* __restrict__ wgt, const float* __restrict__ mask,
    float* __restrict__ out, int N, int layer0)
{
    const int warp = (blockIdx.x * blockDim.x + threadIdx.x) >> 5;
    const int lane = threadIdx.x & 31;
    if (warp >= N) return;

    const int   myIdx = adj[warp * KK + lane];
    const float ma    = mask[myIdx];
    // fold t-mask and msg-mask of the gathered rows into the weight
    const float myW   = wgt[warp * KK + lane] * (layer0 ? ma * ma : ma);

    float4 acc = make_float4(0.f, 0.f, 0.f, 0.f);
    #pragma unroll
    for (int j = 0; j < KK; j++) {
        int   nb = __shfl_sync(0xffffffffu, myIdx, j);
        float wj = __shfl_sync(0xffffffffu, myW,   j);
        float4 v = __ldg(((const float4*)(msg + (size_t)nb * DD)) + lane);
        acc.x = fmaf(wj, v.x, acc.x);
        acc.y = fmaf(wj, v.y, acc.y);
        acc.z = fmaf(wj, v.z, acc.z);
        acc.w = fmaf(wj, v.w, acc.w);
    }

    const float m = mask[warp];
    acc.x *= m; acc.y *= m; acc.z *= m; acc.w *= m;   // combined = (...)*mask

    // expmap_zero: tanh(clip(||v||,eps,15)) * v / max(||v||,eps), then *mask
    float ss = acc.x * acc.x + acc.y * acc.y + acc.z * acc.z + acc.w * acc.w;
    #pragma unroll
    for (int o = 16; o > 0; o >>= 1) ss += __shfl_xor_sync(0xffffffffu, ss, o);
    float n1  = sqrtf(ss);
    float nc1 = fminf(fmaxf(n1, 1e-5f), 15.0f);
    float s1  = tanhf(nc1) / fmaxf(n1, 1e-5f) * m;

    float4 e;
    e.x = fmaxf(acc.x * s1, 0.f) * m;
    e.y = fmaxf(acc.y * s1, 0.f) * m;
    e.z = fmaxf(acc.z * s1, 0.f) * m;
    e.w = fmaxf(acc.w * s1, 0.f) * m;

    if (layer0) {
        // next layer's logmap: atanh(clip(||y||,eps,1-1e-5))*y/max(||y||,eps)*mask
        float ss2 = e.x * e.x + e.y * e.y + e.z * e.z + e.w * e.w;
        #pragma unroll
        for (int o = 16; o > 0; o >>= 1) ss2 += __shfl_xor_sync(0xffffffffu, ss2, o);
        float n2  = sqrtf(ss2);
        float nc2 = fminf(fmaxf(n2, 1e-5f), 1.0f - 1e-5f);
        float s2  = atanhf(nc2) / fmaxf(n2, 1e-5f) * m;
        e.x *= s2; e.y *= s2; e.z *= s2; e.w *= s2;
    }

    ((float4*)out)[warp * 32 + lane] = e;
}

// ---------------------------------------------------------------------------

extern "C" void kernel_launch(void* const* d_in, const int* in_sizes, int n_in,
                              void* d_out, int out_size)
{
    const float* node_repr = (const float*)d_in[0];   // [N,128]
    const int*   adj_mat   = (const int*)  d_in[1];   // [N,32]
    const float* weight    = (const float*)d_in[2];   // [N,32]
    const float* mask      = (const float*)d_in[3];   // [N,1]
    const float* msg_w     = (const float*)d_in[4];   // [2,128,128]
    float*       out       = (float*)d_out;

    const int N = in_sizes[0] / DD;

    float* msg; float* xbuf;
    cudaGetSymbolAddress((void**)&msg,  g_msg);
    cudaGetSymbolAddress((void**)&xbuf, g_x);

    const int smemBytes = 4 * ATILE * LDSA * sizeof(float);   // 66 KB
    static int attrSet = 0;
    if (!attrSet) {
        cudaFuncSetAttribute(gemm_kernel,
                             cudaFuncAttributeMaxDynamicSharedMemorySize, smemBytes);
        // agg uses no smem: maximize L1 to raise gather hit rate
        cudaFuncSetAttribute(agg_kernel,
                             cudaFuncAttributePreferredSharedMemoryCarveout, 0);
        attrSet = 1;
    }

    const int nTiles = (N + ATILE - 1) / ATILE;
    int gemmBlocks = 296;                // persistent, 2 CTA/SM
    if (gemmBlocks > nTiles) gemmBlocks = nTiles;
    const int aggBlocks = (N * 32 + 255) / 256;

    const float* W0 = msg_w;
    const float* W1 = msg_w + DD * DD;

    gemm_kernel<<<gemmBlocks, 256, smemBytes>>>(node_repr, W0, msg, N);
    agg_kernel <<<aggBlocks, 256>>>(msg, adj_mat, weight, mask, xbuf, N, 1);
    gemm_kernel<<<gemmBlocks, 256, smemBytes>>>(xbuf, W1, msg, N);
    agg_kernel <<<aggBlocks, 256>>>(msg, adj_mat, weight, mask, out, N, 0);
}

// round 15
// speedup vs baseline: 1.6187x; 1.2228x over previous
#include <cuda_runtime.h>
#include <mma.h>
#include <math.h>

// ---------------------------------------------------------------------------
// RiemannianGNN, 2-layer Poincare GNN — split kernels.
//   gemm:  msg = x @ W   (raw mma.sync tf32 m16n8k8; B (=W) in registers,
//          loaded once; A via cp.async 4-buffer ring, depth 2;
//          epilogue packs fp32 acc -> bf16x2, msg stored bf16)
//   agg:   combined = sum_k (w*maskfac[adj]) * msg[adj],  * mask[n]
//          bf16 rows unpacked with SHF/LOP (fast alu pipe, no F2F converts);
//          out = relu(expmap(.)*mask)*mask  (+ fused logmap*mask for layer 0)
// ---------------------------------------------------------------------------

#define NMAX 50000
#define DD 128
#define KK 32
#define LDSA 132        // padded A stride (floats)
#define ATILE 32        // rows per pipelined A tile

__device__ __align__(16) unsigned short g_msg[NMAX * DD];  // bf16 msg buffer
__device__ __align__(16) float g_x[NMAX * DD];             // fp32 inter-layer x

__device__ __forceinline__ void cp_async16(float* smem_dst, const float* gsrc) {
    unsigned s = (unsigned)__cvta_generic_to_shared(smem_dst);
    asm volatile("cp.async.cg.shared.global [%0], [%1], 16;" :: "r"(s), "l"(gsrc));
}
__device__ __forceinline__ void cp_commit() {
    asm volatile("cp.async.commit_group;");
}
__device__ __forceinline__ void cp_wait2() {
    asm volatile("cp.async.wait_group 2;");
}

// D(16x8) += A(16x8,row) * B(8x8,col), tf32 inputs, f32 accum
__device__ __forceinline__ void mma_tf32(float* d,
    unsigned a0, unsigned a1, unsigned a2, unsigned a3,
    unsigned b0, unsigned b1)
{
    asm volatile(
        "mma.sync.aligned.m16n8k8.row.col.f32.tf32.tf32.f32 "
        "{%0,%1,%2,%3}, {%4,%5,%6,%7}, {%8,%9}, {%0,%1,%2,%3};"
        : "+f"(d[0]), "+f"(d[1]), "+f"(d[2]), "+f"(d[3])
        : "r"(a0), "r"(a1), "r"(a2), "r"(a3), "r"(b0), "r"(b1));
}

__device__ __forceinline__ unsigned to_tf32_bits(float v) {
    return __float_as_uint(nvcuda::wmma::__float_to_tf32(v));
}
// pack {hi,lo} fp32 -> bf16x2 word (hi in bits[31:16], lo in bits[15:0])
__device__ __forceinline__ unsigned pack_bf16x2(float hi, float lo) {
    unsigned d;
    asm("cvt.rn.bf16x2.f32 %0, %1, %2;" : "=r"(d) : "f"(hi), "f"(lo));
    return d;
}

// ---------------- persistent GEMM: out(bf16) = x @ W, B-in-registers -------
// 8 warps; warp w owns output cols [w*16, w*16+16): 2 n8 groups.
__global__ __launch_bounds__(256, 2) void gemm_kernel(
    const float* __restrict__ x, const float* __restrict__ W,
    unsigned short* __restrict__ out, int N)
{
    extern __shared__ float sm[];
    float* Ab[4];
    Ab[0] = sm;
    Ab[1] = Ab[0] + ATILE * LDSA;
    Ab[2] = Ab[1] + ATILE * LDSA;
    Ab[3] = Ab[2] + ATILE * LDSA;

    const int tid  = threadIdx.x;
    const int w    = tid >> 5;
    const int lane = tid & 31;
    const int g    = lane >> 2;      // groupID
    const int t    = lane & 3;       // threadID_in_group
    const int n0   = w * 16;         // warp's output column base

    // B fragments in registers, loaded once from global W
    unsigned breg[16][2][2];
    #pragma unroll
    for (int ks = 0; ks < 16; ks++) {
        const int k0 = ks * 8 + t;
        #pragma unroll
        for (int ng = 0; ng < 2; ng++) {
            const int col = n0 + ng * 8 + g;
            breg[ks][ng][0] = to_tf32_bits(W[(size_t)k0       * DD + col]);
            breg[ks][ng][1] = to_tf32_bits(W[(size_t)(k0 + 4) * DD + col]);
        }
    }

    const int G = gridDim.x;
    const int nTiles = (N + ATILE - 1) / ATILE;

    auto loadA = [&](int tt, float* buf) {
        if (tt >= nTiles) return;
        const int t0 = tt * ATILE;
        #pragma unroll
        for (int i = 0; i < 4; i++) {
            int idx = tid + i * 256;
            int r = idx >> 5, c4 = idx & 31;
            int n = t0 + r;
            float* dst = buf + r * LDSA + c4 * 4;
            if (n < N) {
                cp_async16(dst, x + (size_t)n * DD + c4 * 4);
            } else {
                dst[0] = 0.f; dst[1] = 0.f; dst[2] = 0.f; dst[3] = 0.f;
            }
        }
    };

    loadA(blockIdx.x,     Ab[0]); cp_commit();
    loadA(blockIdx.x + G, Ab[1]); cp_commit();

    int it = 0;
    for (int tile = blockIdx.x; tile < nTiles; tile += G, it++) {
        loadA(tile + 2 * G, Ab[(it + 2) & 3]);
        cp_commit();
        cp_wait2();
        __syncthreads();

        const float* A  = Ab[it & 3];
        const float* Al = A + g * LDSA + t;

        float acc[2][2][4];
        #pragma unroll
        for (int rg = 0; rg < 2; rg++)
            #pragma unroll
            for (int ng = 0; ng < 2; ng++)
                #pragma unroll
                for (int i = 0; i < 4; i++) acc[rg][ng][i] = 0.f;

        #pragma unroll
        for (int ks = 0; ks < 16; ks++) {
            #pragma unroll
            for (int rg = 0; rg < 2; rg++) {
                const float* Ar = Al + rg * 16 * LDSA + ks * 8;
                unsigned a0 = __float_as_uint(Ar[0]);
                unsigned a1 = __float_as_uint(Ar[8 * LDSA]);
                unsigned a2 = __float_as_uint(Ar[4]);
                unsigned a3 = __float_as_uint(Ar[8 * LDSA + 4]);
                #pragma unroll
                for (int ng = 0; ng < 2; ng++)
                    mma_tf32(acc[rg][ng], a0, a1, a2, a3,
                             breg[ks][ng][0], breg[ks][ng][1]);
            }
        }

        // epilogue: pack (col 2t, 2t+1) -> one bf16x2 word, STG.32
        const int t0 = tile * ATILE;
        #pragma unroll
        for (int rg = 0; rg < 2; rg++) {
            #pragma unroll
            for (int ng = 0; ng < 2; ng++) {
                const int row = t0 + rg * 16 + g;
                const int col = n0 + ng * 8 + 2 * t;     // even
                if (row < N)
                    *(unsigned*)(out + (size_t)row * DD + col) =
                        pack_bf16x2(acc[rg][ng][1], acc[rg][ng][0]);
                if (row + 8 < N)
                    *(unsigned*)(out + (size_t)(row + 8) * DD + col) =
                        pack_bf16x2(acc[rg][ng][3], acc[rg][ng][2]);
            }
        }
    }
}

// ---------------- Aggregation + expmap + relu (+ fused logmap) -------------
// one warp per node; lane l holds cols 4l..4l+3; msg rows are bf16 (256B).
// bf16 -> fp32 via SHF/LOP on the alu pipe (no slow F2F converts).
__global__ __launch_bounds__(256, 8) void agg_kernel(
    const unsigned short* __restrict__ msg, const int* __restrict__ adj,
    const float* __restrict__ wgt, const float* __restrict__ mask,
    float* __restrict__ out, int N, int layer0)
{
    const int warp = (blockIdx.x * blockDim.x + threadIdx.x) >> 5;
    const int lane = threadIdx.x & 31;
    if (warp >= N) return;

    const int   myIdx = adj[warp * KK + lane];
    const float ma    = mask[myIdx];
    const float myW   = wgt[warp * KK + lane] * (layer0 ? ma * ma : ma);

    const uint2* mrows = (const uint2*)msg;   // 32 uint2 per 128-col row

    float a0 = 0.f, a1 = 0.f, a2 = 0.f, a3 = 0.f;
    #pragma unroll
    for (int j = 0; j < KK; j++) {
        int   nb = __shfl_sync(0xffffffffu, myIdx, j);
        float wj = __shfl_sync(0xffffffffu, myW,   j);
        uint2 r  = __ldg(mrows + (size_t)nb * 32 + lane);
        float v0 = __uint_as_float(r.x << 16);
        float v1 = __uint_as_float(r.x & 0xffff0000u);
        float v2 = __uint_as_float(r.y << 16);
        float v3 = __uint_as_float(r.y & 0xffff0000u);
        a0 = fmaf(wj, v0, a0);
        a1 = fmaf(wj, v1, a1);
        a2 = fmaf(wj, v2, a2);
        a3 = fmaf(wj, v3, a3);
    }

    const float m = mask[warp];
    a0 *= m; a1 *= m; a2 *= m; a3 *= m;       // combined = (...)*mask

    // expmap_zero: tanh(clip(||v||,eps,15)) * v / max(||v||,eps), then *mask
    float ss = a0 * a0 + a1 * a1 + a2 * a2 + a3 * a3;
    #pragma unroll
    for (int o = 16; o > 0; o >>= 1) ss += __shfl_xor_sync(0xffffffffu, ss, o);
    float n1  = sqrtf(ss);
    float nc1 = fminf(fmaxf(n1, 1e-5f), 15.0f);
    float s1  = tanhf(nc1) / fmaxf(n1, 1e-5f) * m;

    float e0 = fmaxf(a0 * s1, 0.f) * m;       // relu(...)*mask
    float e1 = fmaxf(a1 * s1, 0.f) * m;
    float e2 = fmaxf(a2 * s1, 0.f) * m;
    float e3 = fmaxf(a3 * s1, 0.f) * m;

    if (layer0) {
        // next layer's logmap: atanh(clip(||y||,eps,1-1e-5))*y/max(||y||,eps)*mask
        float ss2 = e0 * e0 + e1 * e1 + e2 * e2 + e3 * e3;
        #pragma unroll
        for (int o = 16; o > 0; o >>= 1) ss2 += __shfl_xor_sync(0xffffffffu, ss2, o);
        float n2  = sqrtf(ss2);
        float nc2 = fminf(fmaxf(n2, 1e-5f), 1.0f - 1e-5f);
        float s2  = atanhf(nc2) / fmaxf(n2, 1e-5f) * m;
        e0 *= s2; e1 *= s2; e2 *= s2; e3 *= s2;
    }

    float4 e = make_float4(e0, e1, e2, e3);
    ((float4*)out)[warp * 32 + lane] = e;
}

// ---------------------------------------------------------------------------

extern "C" void kernel_launch(void* const* d_in, const int* in_sizes, int n_in,
                              void* d_out, int out_size)
{
    const float* node_repr = (const float*)d_in[0];   // [N,128]
    const int*   adj_mat   = (const int*)  d_in[1];   // [N,32]
    const float* weight    = (const float*)d_in[2];   // [N,32]
    const float* mask      = (const float*)d_in[3];   // [N,1]
    const float* msg_w     = (const float*)d_in[4];   // [2,128,128]
    float*       out       = (float*)d_out;

    const int N = in_sizes[0] / DD;

    unsigned short* msg; float* xbuf;
    cudaGetSymbolAddress((void**)&msg,  g_msg);
    cudaGetSymbolAddress((void**)&xbuf, g_x);

    const int smemBytes = 4 * ATILE * LDSA * sizeof(float);   // 66 KB
    static int attrSet = 0;
    if (!attrSet) {
        cudaFuncSetAttribute(gemm_kernel,
                             cudaFuncAttributeMaxDynamicSharedMemorySize, smemBytes);
        // agg uses no smem: maximize L1 to raise gather hit rate
        cudaFuncSetAttribute(agg_kernel,
                             cudaFuncAttributePreferredSharedMemoryCarveout, 0);
        attrSet = 1;
    }

    const int nTiles = (N + ATILE - 1) / ATILE;
    int gemmBlocks = 296;                // persistent, 2 CTA/SM
    if (gemmBlocks > nTiles) gemmBlocks = nTiles;
    const int aggBlocks = (N * 32 + 255) / 256;

    const float* W0 = msg_w;
    const float* W1 = msg_w + DD * DD;

    gemm_kernel<<<gemmBlocks, 256, smemBytes>>>(node_repr, W0, msg, N);
    agg_kernel <<<aggBlocks, 256>>>(msg, adj_mat, weight, mask, xbuf, N, 1);
    gemm_kernel<<<gemmBlocks, 256, smemBytes>>>(xbuf, W1, msg, N);
    agg_kernel <<<aggBlocks, 256>>>(msg, adj_mat, weight, mask, out, N, 0);
}

// round 16
// speedup vs baseline: 1.7494x; 1.0807x over previous
#include <cuda_runtime.h>
#include <mma.h>
#include <math.h>

// ---------------------------------------------------------------------------
// RiemannianGNN, 2-layer Poincare GNN — split kernels.
//   gemm:  msg = x @ W   (raw mma.sync tf32 m16n8k8; B (=W) in registers,
//          loaded once; A via cp.async 4-buffer ring, depth 2;
//          epilogue packs fp32 acc -> bf16x2, msg stored bf16)
//   agg:   combined = sum_k (w*maskfac[adj]) * msg[adj],  * mask[n]
//          bf16 unpack via SHF/LOP (alu pipe); packed fma.rn.f32x2 (2 elems
//          per issue); {wEff,idx} broadcast via one LDS.64 instead of 2 SHFL;
//          out = relu(expmap(.)*mask)*mask  (+ fused logmap*mask for layer 0)
// ---------------------------------------------------------------------------

#define NMAX 50000
#define DD 128
#define KK 32
#define LDSA 132        // padded A stride (floats)
#define ATILE 32        // rows per pipelined A tile

__device__ __align__(16) unsigned short g_msg[NMAX * DD];  // bf16 msg buffer
__device__ __align__(16) float g_x[NMAX * DD];             // fp32 inter-layer x

__device__ __forceinline__ void cp_async16(float* smem_dst, const float* gsrc) {
    unsigned s = (unsigned)__cvta_generic_to_shared(smem_dst);
    asm volatile("cp.async.cg.shared.global [%0], [%1], 16;" :: "r"(s), "l"(gsrc));
}
__device__ __forceinline__ void cp_commit() {
    asm volatile("cp.async.commit_group;");
}
__device__ __forceinline__ void cp_wait2() {
    asm volatile("cp.async.wait_group 2;");
}

// D(16x8) += A(16x8,row) * B(8x8,col), tf32 inputs, f32 accum
__device__ __forceinline__ void mma_tf32(float* d,
    unsigned a0, unsigned a1, unsigned a2, unsigned a3,
    unsigned b0, unsigned b1)
{
    asm volatile(
        "mma.sync.aligned.m16n8k8.row.col.f32.tf32.tf32.f32 "
        "{%0,%1,%2,%3}, {%4,%5,%6,%7}, {%8,%9}, {%0,%1,%2,%3};"
        : "+f"(d[0]), "+f"(d[1]), "+f"(d[2]), "+f"(d[3])
        : "r"(a0), "r"(a1), "r"(a2), "r"(a3), "r"(b0), "r"(b1));
}

__device__ __forceinline__ unsigned to_tf32_bits(float v) {
    return __float_as_uint(nvcuda::wmma::__float_to_tf32(v));
}
// pack {hi,lo} fp32 -> bf16x2 word (hi in bits[31:16], lo in bits[15:0])
__device__ __forceinline__ unsigned pack_bf16x2(float hi, float lo) {
    unsigned d;
    asm("cvt.rn.bf16x2.f32 %0, %1, %2;" : "=r"(d) : "f"(hi), "f"(lo));
    return d;
}

// packed f32x2 helpers (sm_100+); fma.rn per element == scalar fmaf order
__device__ __forceinline__ unsigned long long pack_f32x2(unsigned lo, unsigned hi) {
    unsigned long long d;
    asm("mov.b64 %0, {%1, %2};" : "=l"(d) : "r"(lo), "r"(hi));
    return d;
}
__device__ __forceinline__ void ffma2(unsigned long long& d,
                                      unsigned long long a, unsigned long long b) {
    asm("fma.rn.f32x2 %0, %1, %2, %0;" : "+l"(d) : "l"(a), "l"(b));
}
__device__ __forceinline__ void unpack_f32x2(unsigned long long v,
                                             float& lo, float& hi) {
    unsigned a, b;
    asm("mov.b64 {%0, %1}, %2;" : "=r"(a), "=r"(b) : "l"(v));
    lo = __uint_as_float(a);
    hi = __uint_as_float(b);
}

// ---------------- persistent GEMM: out(bf16) = x @ W, B-in-registers -------
// 8 warps; warp w owns output cols [w*16, w*16+16): 2 n8 groups.
__global__ __launch_bounds__(256, 2) void gemm_kernel(
    const float* __restrict__ x, const float* __restrict__ W,
    unsigned short* __restrict__ out, int N)
{
    extern __shared__ float sm[];
    float* Ab[4];
    Ab[0] = sm;
    Ab[1] = Ab[0] + ATILE * LDSA;
    Ab[2] = Ab[1] + ATILE * LDSA;
    Ab[3] = Ab[2] + ATILE * LDSA;

    const int tid  = threadIdx.x;
    const int w    = tid >> 5;
    const int lane = tid & 31;
    const int g    = lane >> 2;      // groupID
    const int t    = lane & 3;       // threadID_in_group
    const int n0   = w * 16;         // warp's output column base

    // B fragments in registers, loaded once from global W
    unsigned breg[16][2][2];
    #pragma unroll
    for (int ks = 0; ks < 16; ks++) {
        const int k0 = ks * 8 + t;
        #pragma unroll
        for (int ng = 0; ng < 2; ng++) {
            const int col = n0 + ng * 8 + g;
            breg[ks][ng][0] = to_tf32_bits(W[(size_t)k0       * DD + col]);
            breg[ks][ng][1] = to_tf32_bits(W[(size_t)(k0 + 4) * DD + col]);
        }
    }

    const int G = gridDim.x;
    const int nTiles = (N + ATILE - 1) / ATILE;

    auto loadA = [&](int tt, float* buf) {
        if (tt >= nTiles) return;
        const int t0 = tt * ATILE;
        #pragma unroll
        for (int i = 0; i < 4; i++) {
            int idx = tid + i * 256;
            int r = idx >> 5, c4 = idx & 31;
            int n = t0 + r;
            float* dst = buf + r * LDSA + c4 * 4;
            if (n < N) {
                cp_async16(dst, x + (size_t)n * DD + c4 * 4);
            } else {
                dst[0] = 0.f; dst[1] = 0.f; dst[2] = 0.f; dst[3] = 0.f;
            }
        }
    };

    loadA(blockIdx.x,     Ab[0]); cp_commit();
    loadA(blockIdx.x + G, Ab[1]); cp_commit();

    int it = 0;
    for (int tile = blockIdx.x; tile < nTiles; tile += G, it++) {
        loadA(tile + 2 * G, Ab[(it + 2) & 3]);
        cp_commit();
        cp_wait2();
        __syncthreads();

        const float* A  = Ab[it & 3];
        const float* Al = A + g * LDSA + t;

        float acc[2][2][4];
        #pragma unroll
        for (int rg = 0; rg < 2; rg++)
            #pragma unroll
            for (int ng = 0; ng < 2; ng++)
                #pragma unroll
                for (int i = 0; i < 4; i++) acc[rg][ng][i] = 0.f;

        #pragma unroll
        for (int ks = 0; ks < 16; ks++) {
            #pragma unroll
            for (int rg = 0; rg < 2; rg++) {
                const float* Ar = Al + rg * 16 * LDSA + ks * 8;
                unsigned a0 = __float_as_uint(Ar[0]);
                unsigned a1 = __float_as_uint(Ar[8 * LDSA]);
                unsigned a2 = __float_as_uint(Ar[4]);
                unsigned a3 = __float_as_uint(Ar[8 * LDSA + 4]);
                #pragma unroll
                for (int ng = 0; ng < 2; ng++)
                    mma_tf32(acc[rg][ng], a0, a1, a2, a3,
                             breg[ks][ng][0], breg[ks][ng][1]);
            }
        }

        // epilogue: pack (col 2t, 2t+1) -> one bf16x2 word, STG.32
        const int t0 = tile * ATILE;
        #pragma unroll
        for (int rg = 0; rg < 2; rg++) {
            #pragma unroll
            for (int ng = 0; ng < 2; ng++) {
                const int row = t0 + rg * 16 + g;
                const int col = n0 + ng * 8 + 2 * t;     // even
                if (row < N)
                    *(unsigned*)(out + (size_t)row * DD + col) =
                        pack_bf16x2(acc[rg][ng][1], acc[rg][ng][0]);
                if (row + 8 < N)
                    *(unsigned*)(out + (size_t)(row + 8) * DD + col) =
                        pack_bf16x2(acc[rg][ng][3], acc[rg][ng][2]);
            }
        }
    }
}

// ---------------- Aggregation + expmap + relu (+ fused logmap) -------------
// one warp per node; lane l holds cols 4l..4l+3; msg rows are bf16 (256B).
// Per-j broadcast via one LDS.64 (uniform address) of packed {idx, wEff};
// accumulation via packed fma.rn.f32x2 (identical rounding/order to scalar).
__global__ __launch_bounds__(256, 8) void agg_kernel(
    const unsigned short* __restrict__ msg, const int* __restrict__ adj,
    const float* __restrict__ wgt, const float* __restrict__ mask,
    float* __restrict__ out, int N, int layer0)
{
    __shared__ unsigned long long sidw[8][KK];   // 2 KB: per-warp {idx, wEff}

    const int warp = (blockIdx.x * blockDim.x + threadIdx.x) >> 5;
    const int wrp  = (threadIdx.x >> 5);
    const int lane = threadIdx.x & 31;
    if (warp >= N) return;

    const int   myIdx = adj[warp * KK + lane];
    const float ma    = mask[myIdx];
    const float myW   = wgt[warp * KK + lane] * (layer0 ? ma * ma : ma);

    // stage packed {wEff(hi), idx(lo)} for this warp's 32 neighbors
    sidw[wrp][lane] = ((unsigned long long)__float_as_uint(myW) << 32)
                      | (unsigned)myIdx;
    __syncwarp();

    const uint2* mrows = (const uint2*)msg;   // 32 uint2 per 128-col row

    unsigned long long A01 = 0ull, A23 = 0ull;   // {a0,a1}, {a2,a3} as f32x2
    #pragma unroll
    for (int j = 0; j < KK; j++) {
        const unsigned long long p = sidw[wrp][j];   // LDS.64 broadcast
        const int      nb = (int)(unsigned)p;
        const unsigned wb = (unsigned)(p >> 32);
        uint2 r  = __ldg(mrows + (size_t)nb * 32 + lane);
        unsigned long long v01 = pack_f32x2(r.x << 16, r.x & 0xffff0000u);
        unsigned long long v23 = pack_f32x2(r.y << 16, r.y & 0xffff0000u);
        unsigned long long w2  = pack_f32x2(wb, wb);
        ffma2(A01, v01, w2);
        ffma2(A23, v23, w2);
    }

    float a0, a1, a2, a3;
    unpack_f32x2(A01, a0, a1);
    unpack_f32x2(A23, a2, a3);

    const float m = mask[warp];
    a0 *= m; a1 *= m; a2 *= m; a3 *= m;       // combined = (...)*mask

    // expmap_zero: tanh(clip(||v||,eps,15)) * v / max(||v||,eps), then *mask
    float ss = a0 * a0 + a1 * a1 + a2 * a2 + a3 * a3;
    #pragma unroll
    for (int o = 16; o > 0; o >>= 1) ss += __shfl_xor_sync(0xffffffffu, ss, o);
    float n1  = sqrtf(ss);
    float nc1 = fminf(fmaxf(n1, 1e-5f), 15.0f);
    float s1  = tanhf(nc1) / fmaxf(n1, 1e-5f) * m;

    float e0 = fmaxf(a0 * s1, 0.f) * m;       // relu(...)*mask
    float e1 = fmaxf(a1 * s1, 0.f) * m;
    float e2 = fmaxf(a2 * s1, 0.f) * m;
    float e3 = fmaxf(a3 * s1, 0.f) * m;

    if (layer0) {
        // next layer's logmap: atanh(clip(||y||,eps,1-1e-5))*y/max(||y||,eps)*mask
        float ss2 = e0 * e0 + e1 * e1 + e2 * e2 + e3 * e3;
        #pragma unroll
        for (int o = 16; o > 0; o >>= 1) ss2 += __shfl_xor_sync(0xffffffffu, ss2, o);
        float n2  = sqrtf(ss2);
        float nc2 = fminf(fmaxf(n2, 1e-5f), 1.0f - 1e-5f);
        float s2  = atanhf(nc2) / fmaxf(n2, 1e-5f) * m;
        e0 *= s2; e1 *= s2; e2 *= s2; e3 *= s2;
    }

    float4 e = make_float4(e0, e1, e2, e3);
    ((float4*)out)[warp * 32 + lane] = e;
}

// ---------------------------------------------------------------------------

extern "C" void kernel_launch(void* const* d_in, const int* in_sizes, int n_in,
                              void* d_out, int out_size)
{
    const float* node_repr = (const float*)d_in[0];   // [N,128]
    const int*   adj_mat   = (const int*)  d_in[1];   // [N,32]
    const float* weight    = (const float*)d_in[2];   // [N,32]
    const float* mask      = (const float*)d_in[3];   // [N,1]
    const float* msg_w     = (const float*)d_in[4];   // [2,128,128]
    float*       out       = (float*)d_out;

    const int N = in_sizes[0] / DD;

    unsigned short* msg; float* xbuf;
    cudaGetSymbolAddress((void**)&msg,  g_msg);
    cudaGetSymbolAddress((void**)&xbuf, g_x);

    const int smemBytes = 4 * ATILE * LDSA * sizeof(float);   // 66 KB
    static int attrSet = 0;
    if (!attrSet) {
        cudaFuncSetAttribute(gemm_kernel,
                             cudaFuncAttributeMaxDynamicSharedMemorySize, smemBytes);
        attrSet = 1;
    }

    const int nTiles = (N + ATILE - 1) / ATILE;
    int gemmBlocks = 296;                // persistent, 2 CTA/SM
    if (gemmBlocks > nTiles) gemmBlocks = nTiles;
    const int aggBlocks = (N * 32 + 255) / 256;

    const float* W0 = msg_w;
    const float* W1 = msg_w + DD * DD;

    gemm_kernel<<<gemmBlocks, 256, smemBytes>>>(node_repr, W0, msg, N);
    agg_kernel <<<aggBlocks, 256>>>(msg, adj_mat, weight, mask, xbuf, N, 1);
    gemm_kernel<<<gemmBlocks, 256, smemBytes>>>(xbuf, W1, msg, N);
    agg_kernel <<<aggBlocks, 256>>>(msg, adj_mat, weight, mask, out, N, 0);
}